// round 5
// baseline (speedup 1.0000x reference)
#include <cuda_runtime.h>
#include <cuda_bf16.h>
#include <cstdint>

// IntraAgg: segment-mean neighbor aggregation (TMA-bulk gather pipeline).
//   d_in[0] features    float32 [100000*256]
//   d_in[1] neigh_idx   int32   [524288]
//   d_in[2] segment_ids int32   [524288] (sorted ascending)
//   d_in[3] self_feats  float32 [16384*256]
// output: float32 [16384*512] = concat(self - agg, agg)

#define D_FEAT   256
#define TPB      64               // one float4 per thread per row
#define N_BATCH  16384
#define HALF     4                // rows per pipeline half
#define ROW_B    (D_FEAT * 4)     // 1024 bytes per feature row

__device__ int g_seg_start[N_BATCH + 1];

__global__ void seg_bounds_kernel(const int* __restrict__ seg_ids, int n_edges)
{
    const int e = blockIdx.x * blockDim.x + threadIdx.x;
    if (e >= n_edges) return;
    const int s_cur  = __ldg(seg_ids + e);
    const int s_prev = (e == 0) ? -1 : __ldg(seg_ids + e - 1);
    for (int b = s_prev + 1; b <= s_cur; ++b)
        g_seg_start[b] = e;
    if (e == n_edges - 1)
        for (int b = s_cur + 1; b <= N_BATCH; ++b)
            g_seg_start[b] = n_edges;
}

__device__ __forceinline__ uint32_t smem_u32(const void* p)
{
    return (uint32_t)__cvta_generic_to_shared(p);
}

__device__ __forceinline__ void mbar_init(uint32_t mbar, uint32_t count)
{
    asm volatile("mbarrier.init.shared.b64 [%0], %1;" :: "r"(mbar), "r"(count) : "memory");
}

__device__ __forceinline__ void mbar_expect_tx(uint32_t mbar, uint32_t bytes)
{
    asm volatile("mbarrier.arrive.expect_tx.shared.b64 _, [%0], %1;"
                 :: "r"(mbar), "r"(bytes) : "memory");
}

__device__ __forceinline__ void mbar_wait(uint32_t mbar, uint32_t parity)
{
    asm volatile(
        "{\n\t"
        ".reg .pred P;\n\t"
        "WAIT_%=:\n\t"
        "mbarrier.try_wait.parity.acquire.cta.shared::cta.b64 P, [%0], %1, 0x989680;\n\t"
        "@P bra.uni DONE_%=;\n\t"
        "bra.uni WAIT_%=;\n\t"
        "DONE_%=:\n\t"
        "}"
        :: "r"(mbar), "r"(parity) : "memory");
}

__device__ __forceinline__ void bulk_copy_row(uint32_t dst_smem, const void* src, uint32_t mbar)
{
    asm volatile(
        "cp.async.bulk.shared::cta.global.mbarrier::complete_tx::bytes [%0], [%1], %2, [%3];"
        :: "r"(dst_smem), "l"(src), "n"(ROW_B), "r"(mbar) : "memory");
}

__global__ __launch_bounds__(TPB) void intra_agg_kernel(
    const float* __restrict__ features,
    const int* __restrict__ neigh_idx,
    const float* __restrict__ self_feats,
    float* __restrict__ out)
{
    __shared__ __align__(1024) float buf[2][HALF][D_FEAT];
    __shared__ __align__(8) unsigned long long mbar_s[2];

    const int b   = blockIdx.x;
    const int tid = threadIdx.x;

    const int start = g_seg_start[b];
    const int cnt   = g_seg_start[b + 1] - start;
    const int nhalf = (cnt + HALF - 1) / HALF;

    const uint32_t mbar0 = smem_u32(&mbar_s[0]);
    const uint32_t mbar1 = smem_u32(&mbar_s[1]);

    if (tid == 0) {
        mbar_init(mbar0, 1);
        mbar_init(mbar1, 1);
    }
    __syncthreads();

    // producer: issue all rows of half h into buf[h&1]
    auto issue_half = [&](int h) {
        const int base = h * HALF;
        const int k    = min(HALF, cnt - base);
        const uint32_t mb = (h & 1) ? mbar1 : mbar0;
        mbar_expect_tx(mb, (uint32_t)k * ROW_B);
        #pragma unroll
        for (int j = 0; j < HALF; ++j) {
            if (j < k) {
                const int n = __ldg(neigh_idx + start + base + j);
                bulk_copy_row(smem_u32(&buf[h & 1][j][0]),
                              features + (size_t)n * D_FEAT, mb);
            }
        }
    };

    if (tid == 0 && nhalf > 0) issue_half(0);

    float4 acc0 = make_float4(0.f, 0.f, 0.f, 0.f);
    float4 acc1 = make_float4(0.f, 0.f, 0.f, 0.f);

    int ph0 = 0, ph1 = 0;
    for (int h = 0; h < nhalf; ++h) {
        const int cur = h & 1;
        if (tid == 0 && h + 1 < nhalf) issue_half(h + 1);

        if (cur == 0) { mbar_wait(mbar0, ph0); ph0 ^= 1; }
        else          { mbar_wait(mbar1, ph1); ph1 ^= 1; }

        const int k = min(HALF, cnt - h * HALF);
        const float4* bp = reinterpret_cast<const float4*>(&buf[cur][0][0]);
        int j = 0;
        for (; j + 1 < k; j += 2) {
            const float4 f0 = bp[j * (D_FEAT / 4) + tid];
            const float4 f1 = bp[(j + 1) * (D_FEAT / 4) + tid];
            acc0.x += f0.x; acc0.y += f0.y; acc0.z += f0.z; acc0.w += f0.w;
            acc1.x += f1.x; acc1.y += f1.y; acc1.z += f1.z; acc1.w += f1.w;
        }
        if (j < k) {
            const float4 f0 = bp[j * (D_FEAT / 4) + tid];
            acc0.x += f0.x; acc0.y += f0.y; acc0.z += f0.z; acc0.w += f0.w;
        }
        __syncthreads();   // all threads done with buf[cur] -> safe to refill at h+2
    }

    float4 agg;
    const float inv = 1.0f / fmaxf((float)cnt, 1.0f);
    agg.x = (acc0.x + acc1.x) * inv;
    agg.y = (acc0.y + acc1.y) * inv;
    agg.z = (acc0.z + acc1.z) * inv;
    agg.w = (acc0.w + acc1.w) * inv;

    const float4 s = __ldg(reinterpret_cast<const float4*>(self_feats + (size_t)b * D_FEAT) + tid);
    float4 diff;
    diff.x = s.x - agg.x; diff.y = s.y - agg.y;
    diff.z = s.z - agg.z; diff.w = s.w - agg.w;

    float* orow = out + (size_t)b * (2 * D_FEAT);
    reinterpret_cast<float4*>(orow)[tid] = diff;
    reinterpret_cast<float4*>(orow + D_FEAT)[tid] = agg;
}

extern "C" void kernel_launch(void* const* d_in, const int* in_sizes, int n_in,
                              void* d_out, int out_size)
{
    const float* features   = (const float*)d_in[0];
    const int*   neigh_idx  = (const int*)d_in[1];
    const int*   seg_ids    = (const int*)d_in[2];
    const float* self_feats = (const float*)d_in[3];
    float*       out        = (float*)d_out;

    const int n_edges = in_sizes[1];
    const int n_batch = in_sizes[3] / D_FEAT;   // 16384

    seg_bounds_kernel<<<(n_edges + 255) / 256, 256>>>(seg_ids, n_edges);
    intra_agg_kernel<<<n_batch, TPB>>>(features, neigh_idx, self_feats, out);
}

// round 6
// speedup vs baseline: 1.4994x; 1.4994x over previous
#include <cuda_runtime.h>
#include <cuda_bf16.h>
#include <cstdint>

// IntraAgg: segment-mean neighbor aggregation (per-thread cp.async pipeline).
//   d_in[0] features    float32 [100000*256]
//   d_in[1] neigh_idx   int32   [524288]
//   d_in[2] segment_ids int32   [524288] (sorted ascending)
//   d_in[3] self_feats  float32 [16384*256]
// output: float32 [16384*512] = concat(self - agg, agg)

#define D_FEAT   256
#define TPB      64               // one float4 (16B) per thread per row
#define N_BATCH  16384
#define STAGES   8                // ring depth: 8 rows (8KB) in flight per CTA

__device__ int g_seg_start[N_BATCH + 1];

__global__ void seg_bounds_kernel(const int* __restrict__ seg_ids, int n_edges)
{
    const int e = blockIdx.x * blockDim.x + threadIdx.x;
    if (e >= n_edges) return;
    const int s_cur  = __ldg(seg_ids + e);
    const int s_prev = (e == 0) ? -1 : __ldg(seg_ids + e - 1);
    for (int b = s_prev + 1; b <= s_cur; ++b)
        g_seg_start[b] = e;
    if (e == n_edges - 1)
        for (int b = s_cur + 1; b <= N_BATCH; ++b)
            g_seg_start[b] = n_edges;
}

__device__ __forceinline__ uint32_t smem_u32(const void* p)
{
    return (uint32_t)__cvta_generic_to_shared(p);
}

__device__ __forceinline__ void cp16(uint32_t dst, const void* src)
{
    asm volatile(
        "cp.async.cg.shared.global [%0], [%1], 16;\n\t"
        "cp.async.commit_group;"
        :: "r"(dst), "l"(src) : "memory");
}

__global__ __launch_bounds__(TPB) void intra_agg_kernel(
    const float* __restrict__ features,
    const int* __restrict__ neigh_idx,
    const float* __restrict__ self_feats,
    float* __restrict__ out)
{
    // thread t owns column t of every slot: no cross-thread smem sharing,
    // hence no __syncthreads / mbarrier anywhere.
    __shared__ __align__(16) float4 buf[STAGES][TPB];

    const int b   = blockIdx.x;
    const int tid = threadIdx.x;

    const int start = g_seg_start[b];
    const int cnt   = g_seg_start[b + 1] - start;

    const char* fbase = reinterpret_cast<const char*>(features);
    const size_t col_off = (size_t)tid * 16;   // this thread's 16B within a row

    // ---- prologue: batch-load first STAGES indices, then issue their copies
    const int pre = min(cnt, STAGES);
    int pidx[STAGES];
    #pragma unroll
    for (int j = 0; j < STAGES; ++j)
        pidx[j] = (j < pre) ? __ldg(neigh_idx + start + j) : 0;
    #pragma unroll
    for (int j = 0; j < STAGES; ++j)
        if (j < pre)
            cp16(smem_u32(&buf[j][tid]),
                 fbase + (size_t)pidx[j] * (D_FEAT * 4) + col_off);

    float4 acc0 = make_float4(0.f, 0.f, 0.f, 0.f);
    float4 acc1 = make_float4(0.f, 0.f, 0.f, 0.f);

    // ---- steady state: consume row r, refill slot with row r+STAGES.
    // next-index prefetched one iteration ahead to keep the LDG off the
    // critical issue path.
    int r = 0;
    int nx = (STAGES < cnt) ? __ldg(neigh_idx + start + STAGES) : 0;
    #pragma unroll 1
    for (; r + STAGES < cnt; ++r) {
        asm volatile("cp.async.wait_group %0;" :: "n"(STAGES - 1) : "memory");
        const float4 f = buf[r & (STAGES - 1)][tid];
        cp16(smem_u32(&buf[r & (STAGES - 1)][tid]),
             fbase + (size_t)nx * (D_FEAT * 4) + col_off);
        nx = (r + 1 + STAGES < cnt) ? __ldg(neigh_idx + start + r + 1 + STAGES) : 0;
        if (r & 1) { acc1.x += f.x; acc1.y += f.y; acc1.z += f.z; acc1.w += f.w; }
        else       { acc0.x += f.x; acc0.y += f.y; acc0.z += f.z; acc0.w += f.w; }
    }

    // ---- tail: everything outstanding is for rows [r, cnt)
    asm volatile("cp.async.wait_group 0;" ::: "memory");
    #pragma unroll 1
    for (; r < cnt; ++r) {
        const float4 f = buf[r & (STAGES - 1)][tid];
        if (r & 1) { acc1.x += f.x; acc1.y += f.y; acc1.z += f.z; acc1.w += f.w; }
        else       { acc0.x += f.x; acc0.y += f.y; acc0.z += f.z; acc0.w += f.w; }
    }

    float4 agg;
    const float inv = 1.0f / fmaxf((float)cnt, 1.0f);
    agg.x = (acc0.x + acc1.x) * inv;
    agg.y = (acc0.y + acc1.y) * inv;
    agg.z = (acc0.z + acc1.z) * inv;
    agg.w = (acc0.w + acc1.w) * inv;

    const float4 s = __ldg(reinterpret_cast<const float4*>(self_feats + (size_t)b * D_FEAT) + tid);
    float4 diff;
    diff.x = s.x - agg.x; diff.y = s.y - agg.y;
    diff.z = s.z - agg.z; diff.w = s.w - agg.w;

    float* orow = out + (size_t)b * (2 * D_FEAT);
    reinterpret_cast<float4*>(orow)[tid] = diff;
    reinterpret_cast<float4*>(orow + D_FEAT)[tid] = agg;
}

extern "C" void kernel_launch(void* const* d_in, const int* in_sizes, int n_in,
                              void* d_out, int out_size)
{
    const float* features   = (const float*)d_in[0];
    const int*   neigh_idx  = (const int*)d_in[1];
    const int*   seg_ids    = (const int*)d_in[2];
    const float* self_feats = (const float*)d_in[3];
    float*       out        = (float*)d_out;

    const int n_edges = in_sizes[1];
    const int n_batch = in_sizes[3] / D_FEAT;   // 16384

    seg_bounds_kernel<<<(n_edges + 255) / 256, 256>>>(seg_ids, n_edges);
    intra_agg_kernel<<<n_batch, TPB>>>(features, neigh_idx, self_feats, out);
}

// round 7
// speedup vs baseline: 1.6827x; 1.1222x over previous
#include <cuda_runtime.h>
#include <cuda_bf16.h>
#include <cstdint>

// IntraAgg: segment-mean neighbor aggregation.
// Per-thread cp.async ring, 2-rows-per-commit-group, streaming epilogue.
//   d_in[0] features    float32 [100000*256]
//   d_in[1] neigh_idx   int32   [524288]
//   d_in[2] segment_ids int32   [524288] (sorted ascending)
//   d_in[3] self_feats  float32 [16384*256]
// output: float32 [16384*512] = concat(self - agg, agg)

#define D_FEAT   256
#define TPB      64               // one float4 (16B) per thread per row
#define N_BATCH  16384
#define STAGES   8                // ring: 8 rows = 4 groups of 2 (8KB smem)

__device__ int g_seg_start[N_BATCH + 1];

__global__ void seg_bounds_kernel(const int* __restrict__ seg_ids, int n_edges)
{
    const int e = blockIdx.x * blockDim.x + threadIdx.x;
    if (e >= n_edges) return;
    const int s_cur  = __ldg(seg_ids + e);
    const int s_prev = (e == 0) ? -1 : __ldg(seg_ids + e - 1);
    for (int b = s_prev + 1; b <= s_cur; ++b)
        g_seg_start[b] = e;
    if (e == n_edges - 1)
        for (int b = s_cur + 1; b <= N_BATCH; ++b)
            g_seg_start[b] = n_edges;
}

__device__ __forceinline__ uint32_t smem_u32(const void* p)
{
    return (uint32_t)__cvta_generic_to_shared(p);
}

__device__ __forceinline__ void cp16(uint32_t dst, const void* src)
{
    asm volatile("cp.async.cg.shared.global [%0], [%1], 16;"
                 :: "r"(dst), "l"(src) : "memory");
}

__device__ __forceinline__ void cp_commit()
{
    asm volatile("cp.async.commit_group;" ::: "memory");
}

__global__ __launch_bounds__(TPB) void intra_agg_kernel(
    const float* __restrict__ features,
    const int* __restrict__ neigh_idx,
    const float* __restrict__ self_feats,
    float* __restrict__ out)
{
    // thread t owns column t of every slot: no cross-thread smem sharing,
    // hence no __syncthreads / mbarrier anywhere.
    __shared__ __align__(16) float4 buf[STAGES][TPB];

    const int b   = blockIdx.x;
    const int tid = threadIdx.x;

    const int start = g_seg_start[b];
    const int cnt   = g_seg_start[b + 1] - start;
    const int ngroups = (cnt + 1) >> 1;      // groups of 2 rows (last may be 1)

    const char* fbase = reinterpret_cast<const char*>(features);
    const size_t col_off = (size_t)tid * 16;

    // ---- prologue: issue up to 4 groups (8 rows), one commit per group
    #pragma unroll
    for (int gj = 0; gj < 4; ++gj) {
        if (gj < ngroups) {
            const int r0 = 2 * gj;
            const int n0 = __ldg(neigh_idx + start + r0);
            cp16(smem_u32(&buf[r0][tid]), fbase + (size_t)n0 * (D_FEAT * 4) + col_off);
            if (r0 + 1 < cnt) {
                const int n1 = __ldg(neigh_idx + start + r0 + 1);
                cp16(smem_u32(&buf[r0 + 1][tid]), fbase + (size_t)n1 * (D_FEAT * 4) + col_off);
            }
            cp_commit();
        }
    }

    float4 acc0 = make_float4(0.f, 0.f, 0.f, 0.f);
    float4 acc1 = make_float4(0.f, 0.f, 0.f, 0.f);

    // ---- steady state over full groups; group g is ready after wait_group 3.
    int g = 0;
    // prefetch indices of group g+4 (rows 2g+8, 2g+9)
    int nx0 = 0, nx1 = 0;
    if (0 + 4 < ngroups) {
        nx0 = __ldg(neigh_idx + start + 8);
        nx1 = (9 < cnt) ? __ldg(neigh_idx + start + 9) : nx0;
    }
    #pragma unroll 1
    for (; g + 4 < ngroups; ++g) {
        asm volatile("cp.async.wait_group 3;" ::: "memory");
        const int r = 2 * g;
        const int s0 = r & (STAGES - 1);
        const float4 f0 = buf[s0][tid];
        const float4 f1 = buf[s0 + 1][tid];

        // refill slots s0, s0+1 with rows of group g+4
        const int rr = 2 * (g + 4);
        cp16(smem_u32(&buf[s0][tid]), fbase + (size_t)nx0 * (D_FEAT * 4) + col_off);
        if (rr + 1 < cnt)
            cp16(smem_u32(&buf[s0 + 1][tid]), fbase + (size_t)nx1 * (D_FEAT * 4) + col_off);
        cp_commit();

        // prefetch indices for group g+5
        if (g + 5 < ngroups) {
            const int rn = 2 * (g + 5);
            nx0 = __ldg(neigh_idx + start + rn);
            nx1 = (rn + 1 < cnt) ? __ldg(neigh_idx + start + rn + 1) : nx0;
        }

        acc0.x += f0.x; acc0.y += f0.y; acc0.z += f0.z; acc0.w += f0.w;
        acc1.x += f1.x; acc1.y += f1.y; acc1.z += f1.z; acc1.w += f1.w;
    }

    // ---- tail: drain everything, consume rows [2g, cnt)
    asm volatile("cp.async.wait_group 0;" ::: "memory");
    #pragma unroll 1
    for (int r = 2 * g; r < cnt; ++r) {
        const float4 f = buf[r & (STAGES - 1)][tid];
        if (r & 1) { acc1.x += f.x; acc1.y += f.y; acc1.z += f.z; acc1.w += f.w; }
        else       { acc0.x += f.x; acc0.y += f.y; acc0.z += f.z; acc0.w += f.w; }
    }

    float4 agg;
    const float inv = 1.0f / fmaxf((float)cnt, 1.0f);
    agg.x = (acc0.x + acc1.x) * inv;
    agg.y = (acc0.y + acc1.y) * inv;
    agg.z = (acc0.z + acc1.z) * inv;
    agg.w = (acc0.w + acc1.w) * inv;

    // streaming (evict-first) epilogue: don't pollute L2's copy of features
    const float4 s = __ldcs(reinterpret_cast<const float4*>(self_feats + (size_t)b * D_FEAT) + tid);
    float4 diff;
    diff.x = s.x - agg.x; diff.y = s.y - agg.y;
    diff.z = s.z - agg.z; diff.w = s.w - agg.w;

    float* orow = out + (size_t)b * (2 * D_FEAT);
    __stcs(reinterpret_cast<float4*>(orow) + tid, diff);
    __stcs(reinterpret_cast<float4*>(orow + D_FEAT) + tid, agg);
}

extern "C" void kernel_launch(void* const* d_in, const int* in_sizes, int n_in,
                              void* d_out, int out_size)
{
    const float* features   = (const float*)d_in[0];
    const int*   neigh_idx  = (const int*)d_in[1];
    const int*   seg_ids    = (const int*)d_in[2];
    const float* self_feats = (const float*)d_in[3];
    float*       out        = (float*)d_out;

    const int n_edges = in_sizes[1];
    const int n_batch = in_sizes[3] / D_FEAT;   // 16384

    seg_bounds_kernel<<<(n_edges + 255) / 256, 256>>>(seg_ids, n_edges);
    intra_agg_kernel<<<n_batch, TPB>>>(features, neigh_idx, self_feats, out);
}